// round 1
// baseline (speedup 1.0000x reference)
#include <cuda_runtime.h>

// Problem constants (shapes fixed by the dataset; runtime sizes still read
// from in_sizes for loop bounds).
static constexpr int MAX_NC = 50000;
static constexpr int MAX_NG = 3000;
static constexpr int D      = 64;

// Scratch: weighted source features (wf = feat * cj * mask).
__device__ float g_wf_c[MAX_NC * D];      // cells, weighted for 'exp'
__device__ float g_wf_grev[MAX_NG * D];   // genes, weighted for 'reverse-exp'
__device__ float g_wf_ggg[MAX_NG * D];    // genes, weighted for 'co-exp'

// ---------------------------------------------------------------------------
// Zero the output buffer (poisoned to 0xAA by the harness).
// ---------------------------------------------------------------------------
__global__ void zero_out_kernel(float4* __restrict__ out, int n_vec) {
    int i = blockIdx.x * blockDim.x + threadIdx.x;
    if (i < n_vec) out[i] = make_float4(0.f, 0.f, 0.f, 0.f);
}

// ---------------------------------------------------------------------------
// wf = feat * (cj * mask), one weighting.
// ---------------------------------------------------------------------------
__global__ void weight_rows1(const float* __restrict__ feat,
                             const float* __restrict__ cj,
                             const float* __restrict__ mask,
                             float* __restrict__ out, int n_vec) {
    int i = blockIdx.x * blockDim.x + threadIdx.x;
    if (i >= n_vec) return;
    int row = i >> 4;                       // 16 float4 per 64-float row
    float w = __ldg(cj + row) * __ldg(mask + row);
    float4 v = __ldg(((const float4*)feat) + i);
    v.x *= w; v.y *= w; v.z *= w; v.w *= w;
    ((float4*)out)[i] = v;
}

// ---------------------------------------------------------------------------
// Two weightings of the same feature table in one pass (gene table).
// ---------------------------------------------------------------------------
__global__ void weight_rows2(const float* __restrict__ feat,
                             const float* __restrict__ cj1, const float* __restrict__ m1,
                             const float* __restrict__ cj2, const float* __restrict__ m2,
                             float* __restrict__ out1, float* __restrict__ out2,
                             int n_vec) {
    int i = blockIdx.x * blockDim.x + threadIdx.x;
    if (i >= n_vec) return;
    int row = i >> 4;
    float4 v = __ldg(((const float4*)feat) + i);
    float w1 = __ldg(cj1 + row) * __ldg(m1 + row);
    float w2 = __ldg(cj2 + row) * __ldg(m2 + row);
    float4 a = make_float4(v.x * w1, v.y * w1, v.z * w1, v.w * w1);
    float4 b = make_float4(v.x * w2, v.y * w2, v.z * w2, v.w * w2);
    ((float4*)out1)[i] = a;
    ((float4*)out2)[i] = b;
}

// ---------------------------------------------------------------------------
// Edge scatter: out[dst] += alpha * ci[dst] * wf[src], 16 threads per edge,
// float4 per thread, vector reduction (no return) into L2.
// ---------------------------------------------------------------------------
__global__ void edge_scatter(const int* __restrict__ src,
                             const int* __restrict__ dst,
                             const float* __restrict__ wf,
                             const float* __restrict__ ci,
                             float* __restrict__ out,
                             int nE, float alpha) {
    unsigned t = blockIdx.x * blockDim.x + threadIdx.x;
    int e    = (int)(t >> 4);
    int lane = (int)(t & 15u);
    if (e >= nE) return;
    int s = __ldg(src + e);     // 16 lanes read same addr -> L1 broadcast
    int d = __ldg(dst + e);
    float scale = alpha * __ldg(ci + d);
    float4 v = __ldg((const float4*)(wf + (size_t)s * D) + lane);
    v.x *= scale; v.y *= scale; v.z *= scale; v.w *= scale;
    float* p = out + (size_t)d * D + lane * 4;
    asm volatile("red.global.add.v4.f32 [%0], {%1,%2,%3,%4};"
                 :: "l"(p), "f"(v.x), "f"(v.y), "f"(v.z), "f"(v.w)
                 : "memory");
}

// ---------------------------------------------------------------------------
// kernel_launch
// Input order (metadata): c_feat, g_feat, cj_cell, ci_cell, cj_gene, ci_gene,
//   cjj_gene, cii_gene, mask_exp, mask_rev, mask_gg,
//   src_cg, dst_cg, src_gc, dst_gc, src_gg, dst_gg
// Output: concat(c_out [NC*D], g_out [NG*D]) float32.
// ---------------------------------------------------------------------------
extern "C" void kernel_launch(void* const* d_in, const int* in_sizes, int n_in,
                              void* d_out, int out_size) {
    const float* c_feat   = (const float*)d_in[0];
    const float* g_feat   = (const float*)d_in[1];
    const float* cj_cell  = (const float*)d_in[2];
    const float* ci_cell  = (const float*)d_in[3];
    const float* cj_gene  = (const float*)d_in[4];
    const float* ci_gene  = (const float*)d_in[5];
    const float* cjj_gene = (const float*)d_in[6];
    const float* cii_gene = (const float*)d_in[7];
    const float* mask_exp = (const float*)d_in[8];
    const float* mask_rev = (const float*)d_in[9];
    const float* mask_gg  = (const float*)d_in[10];
    const int*   src_cg   = (const int*)d_in[11];
    const int*   dst_cg   = (const int*)d_in[12];
    const int*   src_gc   = (const int*)d_in[13];
    const int*   dst_gc   = (const int*)d_in[14];
    const int*   src_gg   = (const int*)d_in[15];
    const int*   dst_gg   = (const int*)d_in[16];

    const int nc   = in_sizes[0] / D;
    const int ng   = in_sizes[1] / D;
    const int e_cg = in_sizes[11];
    const int e_gc = in_sizes[13];
    const int e_gg = in_sizes[15];

    float* c_out = (float*)d_out;                  // [nc, D]
    float* g_out = (float*)d_out + (size_t)nc * D; // [ng, D]

    float *wf_c, *wf_grev, *wf_ggg;
    cudaGetSymbolAddress((void**)&wf_c,    g_wf_c);
    cudaGetSymbolAddress((void**)&wf_grev, g_wf_grev);
    cudaGetSymbolAddress((void**)&wf_ggg,  g_wf_ggg);

    // 1) zero the output accumulators
    {
        int n_vec = out_size / 4;
        zero_out_kernel<<<(n_vec + 255) / 256, 256>>>((float4*)d_out, n_vec);
    }

    // 2) precompute weighted source features
    {
        int nv = nc * (D / 4);
        weight_rows1<<<(nv + 255) / 256, 256>>>(c_feat, cj_cell, mask_exp, wf_c, nv);
    }
    {
        int nv = ng * (D / 4);
        weight_rows2<<<(nv + 255) / 256, 256>>>(g_feat, cj_gene, mask_rev,
                                                cjj_gene, mask_gg,
                                                wf_grev, wf_ggg, nv);
    }

    // 3) edge scatters (ci and alpha folded into per-edge contribution)
    {
        // cell -> gene ('exp'), alpha1 = 0.5
        long long th = (long long)e_cg * 16;
        int blocks = (int)((th + 255) / 256);
        edge_scatter<<<blocks, 256>>>(src_cg, dst_cg, wf_c, ci_gene, g_out, e_cg, 0.5f);
    }
    {
        // gene -> cell ('reverse-exp'), only relation into cells, alpha = 1
        long long th = (long long)e_gc * 16;
        int blocks = (int)((th + 255) / 256);
        edge_scatter<<<blocks, 256>>>(src_gc, dst_gc, wf_grev, ci_cell, c_out, e_gc, 1.0f);
    }
    {
        // gene -> gene ('co-exp'), (1 - alpha1) = 0.5
        long long th = (long long)e_gg * 16;
        int blocks = (int)((th + 255) / 256);
        edge_scatter<<<blocks, 256>>>(src_gg, dst_gg, wf_ggg, cii_gene, g_out, e_gg, 0.5f);
    }
}

// round 2
// speedup vs baseline: 1.2164x; 1.2164x over previous
#include <cuda_runtime.h>

// Problem constants (shapes fixed by the dataset; runtime sizes still read
// from in_sizes for loop bounds).
static constexpr int MAX_NC = 50000;
static constexpr int MAX_NG = 3000;
static constexpr int D      = 64;
static constexpr int EPT    = 4;   // edges per thread-group (ILP batching)

// Scratch: weighted source features (wf = feat * cj * mask).
__device__ float g_wf_c[MAX_NC * D];      // cells, weighted for 'exp'
__device__ float g_wf_grev[MAX_NG * D];   // genes, weighted for 'reverse-exp'
__device__ float g_wf_ggg[MAX_NG * D];    // genes, weighted for 'co-exp'

// ---------------------------------------------------------------------------
// wf = feat * (cj * mask), one weighting.
// ---------------------------------------------------------------------------
__global__ void weight_rows1(const float* __restrict__ feat,
                             const float* __restrict__ cj,
                             const float* __restrict__ mask,
                             float* __restrict__ out, int n_vec) {
    int i = blockIdx.x * blockDim.x + threadIdx.x;
    if (i >= n_vec) return;
    int row = i >> 4;                       // 16 float4 per 64-float row
    float w = __ldg(cj + row) * __ldg(mask + row);
    float4 v = __ldg(((const float4*)feat) + i);
    v.x *= w; v.y *= w; v.z *= w; v.w *= w;
    ((float4*)out)[i] = v;
}

// ---------------------------------------------------------------------------
// Two weightings of the same feature table in one pass (gene table).
// ---------------------------------------------------------------------------
__global__ void weight_rows2(const float* __restrict__ feat,
                             const float* __restrict__ cj1, const float* __restrict__ m1,
                             const float* __restrict__ cj2, const float* __restrict__ m2,
                             float* __restrict__ out1, float* __restrict__ out2,
                             int n_vec) {
    int i = blockIdx.x * blockDim.x + threadIdx.x;
    if (i >= n_vec) return;
    int row = i >> 4;
    float4 v = __ldg(((const float4*)feat) + i);
    float w1 = __ldg(cj1 + row) * __ldg(m1 + row);
    float w2 = __ldg(cj2 + row) * __ldg(m2 + row);
    float4 a = make_float4(v.x * w1, v.y * w1, v.z * w1, v.w * w1);
    float4 b = make_float4(v.x * w2, v.y * w2, v.z * w2, v.w * w2);
    ((float4*)out1)[i] = a;
    ((float4*)out2)[i] = b;
}

// ---------------------------------------------------------------------------
// Edge scatter with 4-edge ILP batching.
// Thread-group of 16 lanes handles EPT=4 consecutive edges; each lane owns one
// float4 slot of the 64-float feature row. Index loads are batched first, then
// the 4 long-latency gather chains run independently (MLP=4), then 4 vector
// reductions. out[dst] += alpha * ci[dst] * wf[src].
// ---------------------------------------------------------------------------
__global__ void edge_scatter4(const int* __restrict__ src,
                              const int* __restrict__ dst,
                              const float* __restrict__ wf,
                              const float* __restrict__ ci,
                              float* __restrict__ out,
                              int nE, float alpha) {
    unsigned t = blockIdx.x * blockDim.x + threadIdx.x;
    int group = (int)(t >> 4);
    int lane  = (int)(t & 15u);
    int e0 = group * EPT;
    if (e0 >= nE) return;

    int s[EPT], d[EPT];
    bool valid[EPT];
    #pragma unroll
    for (int k = 0; k < EPT; k++) {
        int e = e0 + k;
        valid[k] = (e < nE);
        s[k] = valid[k] ? __ldg(src + e) : 0;
        d[k] = valid[k] ? __ldg(dst + e) : 0;
    }

    float sc[EPT];
    #pragma unroll
    for (int k = 0; k < EPT; k++)
        sc[k] = alpha * __ldg(ci + d[k]);

    float4 v[EPT];
    #pragma unroll
    for (int k = 0; k < EPT; k++)
        v[k] = __ldg((const float4*)(wf + (size_t)s[k] * D) + lane);

    #pragma unroll
    for (int k = 0; k < EPT; k++) {
        if (!valid[k]) continue;
        float4 r = v[k];
        r.x *= sc[k]; r.y *= sc[k]; r.z *= sc[k]; r.w *= sc[k];
        float* p = out + (size_t)d[k] * D + lane * 4;
        asm volatile("red.global.add.v4.f32 [%0], {%1,%2,%3,%4};"
                     :: "l"(p), "f"(r.x), "f"(r.y), "f"(r.z), "f"(r.w)
                     : "memory");
    }
}

// ---------------------------------------------------------------------------
// kernel_launch
// Input order (metadata): c_feat, g_feat, cj_cell, ci_cell, cj_gene, ci_gene,
//   cjj_gene, cii_gene, mask_exp, mask_rev, mask_gg,
//   src_cg, dst_cg, src_gc, dst_gc, src_gg, dst_gg
// Output: concat(c_out [NC*D], g_out [NG*D]) float32.
// ---------------------------------------------------------------------------
extern "C" void kernel_launch(void* const* d_in, const int* in_sizes, int n_in,
                              void* d_out, int out_size) {
    const float* c_feat   = (const float*)d_in[0];
    const float* g_feat   = (const float*)d_in[1];
    const float* cj_cell  = (const float*)d_in[2];
    const float* ci_cell  = (const float*)d_in[3];
    const float* cj_gene  = (const float*)d_in[4];
    const float* ci_gene  = (const float*)d_in[5];
    const float* cjj_gene = (const float*)d_in[6];
    const float* cii_gene = (const float*)d_in[7];
    const float* mask_exp = (const float*)d_in[8];
    const float* mask_rev = (const float*)d_in[9];
    const float* mask_gg  = (const float*)d_in[10];
    const int*   src_cg   = (const int*)d_in[11];
    const int*   dst_cg   = (const int*)d_in[12];
    const int*   src_gc   = (const int*)d_in[13];
    const int*   dst_gc   = (const int*)d_in[14];
    const int*   src_gg   = (const int*)d_in[15];
    const int*   dst_gg   = (const int*)d_in[16];

    const int nc   = in_sizes[0] / D;
    const int ng   = in_sizes[1] / D;
    const int e_cg = in_sizes[11];
    const int e_gc = in_sizes[13];
    const int e_gg = in_sizes[15];

    float* c_out = (float*)d_out;                  // [nc, D]
    float* g_out = (float*)d_out + (size_t)nc * D; // [ng, D]

    float *wf_c, *wf_grev, *wf_ggg;
    cudaGetSymbolAddress((void**)&wf_c,    g_wf_c);
    cudaGetSymbolAddress((void**)&wf_grev, g_wf_grev);
    cudaGetSymbolAddress((void**)&wf_ggg,  g_wf_ggg);

    // 1) zero the output accumulators (poisoned to 0xAA by the harness)
    cudaMemsetAsync(d_out, 0, (size_t)out_size * sizeof(float));

    // 2) precompute weighted source features
    {
        int nv = nc * (D / 4);
        weight_rows1<<<(nv + 255) / 256, 256>>>(c_feat, cj_cell, mask_exp, wf_c, nv);
    }
    {
        int nv = ng * (D / 4);
        weight_rows2<<<(nv + 255) / 256, 256>>>(g_feat, cj_gene, mask_rev,
                                                cjj_gene, mask_gg,
                                                wf_grev, wf_ggg, nv);
    }

    // 3) edge scatters (ci and alpha folded into per-edge contribution)
    auto launch_scatter = [](const int* s, const int* d, const float* wf,
                             const float* ci, float* out, int nE, float alpha) {
        long long groups = (nE + EPT - 1) / EPT;
        long long th = groups * 16;
        int blocks = (int)((th + 255) / 256);
        edge_scatter4<<<blocks, 256>>>(s, d, wf, ci, out, nE, alpha);
    };
    // cell -> gene ('exp'), alpha1 = 0.5
    launch_scatter(src_cg, dst_cg, wf_c, ci_gene, g_out, e_cg, 0.5f);
    // gene -> cell ('reverse-exp'), only relation into cells, alpha = 1
    launch_scatter(src_gc, dst_gc, wf_grev, ci_cell, c_out, e_gc, 1.0f);
    // gene -> gene ('co-exp'), (1 - alpha1) = 0.5
    launch_scatter(src_gg, dst_gg, wf_ggg, cii_gene, g_out, e_gg, 0.5f);
}